// round 5
// baseline (speedup 1.0000x reference)
#include <cuda_runtime.h>
#include <cstdint>

#define BB 512
#define RR 264
#define KK 32
#define SS 9
#define RSTRIDE 36            // padded row stride in floats (144 B, 16B-aligned)
#define NSPLIT 4
#define ROWS_PER 66           // rows per CTA (split across 2 row-halves of 33)
#define NTHREADS 288

typedef unsigned long long ull;

__device__ __constant__ int   c_ends[SS]   = {28, 58, 92, 121, 150, 180, 210, 240, 264};
__device__ __constant__ int   c_starts[SS] = {0, 28, 58, 92, 121, 150, 180, 210, 240};
__device__ __constant__ float c_sizes[SS]  = {28.f, 30.f, 34.f, 29.f, 29.f, 30.f, 30.f, 30.f, 24.f};

__device__ __forceinline__ ull fma2(ull a, ull b, ull c) {
    ull d;
    asm("fma.rn.f32x2 %0, %1, %2, %3;" : "=l"(d) : "l"(a), "l"(b), "l"(c));
    return d;
}
__device__ __forceinline__ ull add2(ull a, ull b) {
    ull d;
    asm("add.rn.f32x2 %0, %1, %2;" : "=l"(d) : "l"(a), "l"(b));
    return d;
}
__device__ __forceinline__ float sum2(ull a) {
    return __uint_as_float((unsigned)(a & 0xffffffffull)) +
           __uint_as_float((unsigned)(a >> 32));
}

extern "C" __global__ void __launch_bounds__(NTHREADS, 2)
gram_kernel(const float* __restrict__ E, float* __restrict__ out)
{
    float* intra = out;
    float* inter = out + (size_t)BB * RR * RR;
    float* adj   = inter + (size_t)BB * SS * SS;

    __shared__ float sE[RR * RSTRIDE];
    __shared__ float sSum[SS * KK];

    const int b     = blockIdx.y;
    const int split = blockIdx.x;
    const int tid   = threadIdx.x;
    const float* Eb = E + (size_t)b * (RR * KK);

    // ---- cooperative load of E[b] into padded smem (float4 coalesced) ----
    for (int i = tid; i < (RR * KK) / 4; i += NTHREADS) {
        float4 v = reinterpret_cast<const float4*>(Eb)[i];
        int row = i >> 3, kq = i & 7;
        *reinterpret_cast<float4*>(&sE[row * RSTRIDE + kq * 4]) = v;
    }
    __syncthreads();

    const bool active = (tid < RR);
    const int  t   = active ? tid : 0;
    const int  rh  = t & 1;          // row half: even tids -> rows [0,33), odd -> [33,66)
    const int  cp  = t >> 1;         // col-pair id (0..131)
    const int  c0  = 2 * cp;

    // two column k-vectors in registers (8 LDS.128 each, one-time)
    ull bv0[16], bv1[16];
    #pragma unroll
    for (int q = 0; q < 8; q++) {
        ulonglong2 t0 = *reinterpret_cast<const ulonglong2*>(&sE[c0 * RSTRIDE + 4 * q]);
        ulonglong2 t1 = *reinterpret_cast<const ulonglong2*>(&sE[(c0 + 1) * RSTRIDE + 4 * q]);
        bv0[2 * q] = t0.x; bv0[2 * q + 1] = t0.y;
        bv1[2 * q] = t1.x; bv1[2 * q + 1] = t1.y;
    }

    // register-resident intra masks for the two columns
    int seg0 = 0, seg1 = 0;
    #pragma unroll
    for (int j = 0; j < SS; j++) {
        seg0 += (c0     >= c_ends[j]) ? 1 : 0;
        seg1 += (c0 + 1 >= c_ends[j]) ? 1 : 0;
    }
    const int lo0 = c_starts[seg0], hi0 = c_ends[seg0];
    const int lo1 = c_starts[seg1], hi1 = c_ends[seg1];

    const int rbase = split * ROWS_PER + rh * 33;
    float* adjp   = adj   + (((size_t)b * RR + rbase) * RR) + c0;
    float* intrap = intra + (((size_t)b * RR + rbase) * RR) + c0;

    for (int it = 0; it < 33; it++) {
        const float* arow = &sE[(rbase + it) * RSTRIDE];
        ull x0 = 0, x1 = 0, y0 = 0, y1 = 0;      // 4 independent chains
        #pragma unroll
        for (int q = 0; q < 8; q++) {
            ulonglong2 ap = *reinterpret_cast<const ulonglong2*>(arow + 4 * q); // LDS.128 bcast
            x0 = fma2(ap.x, bv0[2 * q],     x0);
            x1 = fma2(ap.y, bv0[2 * q + 1], x1);
            y0 = fma2(ap.x, bv1[2 * q],     y0);
            y1 = fma2(ap.y, bv1[2 * q + 1], y1);
        }
        float v0 = sum2(add2(x0, x1));
        float v1 = sum2(add2(y0, y1));
        const int r = rbase + it;
        if (active) {
            float2 av; av.x = v0; av.y = v1;
            *reinterpret_cast<float2*>(adjp) = av;
            float2 iv;
            iv.x = (r >= lo0 && r < hi0) ? v0 : 0.0f;
            iv.y = (r >= lo1 && r < hi1) ? v1 : 0.0f;
            *reinterpret_cast<float2*>(intrap) = iv;
        }
        adjp   += RR;
        intrap += RR;
    }

    // ---- inter-network block means, only split-0 CTAs (one per batch) ----
    if (split == 0) {
        for (int i = tid; i < SS * KK; i += NTHREADS) {
            int s  = i >> 5;
            int d  = i & 31;
            int st = (s == 0) ? 0 : c_ends[s - 1];
            int en = c_ends[s];
            float a = 0.0f;
            for (int rr2 = st; rr2 < en; rr2++) a += sE[rr2 * RSTRIDE + d];
            sSum[i] = a;
        }
        __syncthreads();
        if (tid < SS * SS) {
            int s = tid / SS, tt = tid % SS;
            float a = 0.0f;
            #pragma unroll
            for (int d = 0; d < KK; d++)
                a += sSum[s * KK + d] * sSum[tt * KK + d];
            inter[(size_t)b * SS * SS + tid] = a / (c_sizes[s] * c_sizes[tt]);
        }
    }
}

extern "C" void kernel_launch(void* const* d_in, const int* in_sizes, int n_in,
                              void* d_out, int out_size)
{
    (void)in_sizes; (void)n_in; (void)out_size;
    const float* E = (const float*)d_in[0];
    float* out = (float*)d_out;

    dim3 grid(NSPLIT, BB);
    gram_kernel<<<grid, NTHREADS>>>(E, out);
}